// round 6
// baseline (speedup 1.0000x reference)
#include <cuda_runtime.h>

#define FULLMASK 0xffffffffu
#define EPSF 1e-8f
#define LN_EPSF 1e-5f

static __device__ __forceinline__ float clipf(float x) {
    return fminf(fmaxf(x, -100.0f), 100.0f);
}

// Reduce 4 independent values across a 256-thread block. scratch >= 32 floats.
static __device__ __forceinline__ void blockReduceSum4(float* v, float* scratch, int tid) {
#pragma unroll
    for (int i = 0; i < 4; i++) {
#pragma unroll
        for (int o = 16; o; o >>= 1) v[i] += __shfl_xor_sync(FULLMASK, v[i], o);
    }
    if ((tid & 31) == 0) {
        int w = tid >> 5;
        scratch[w * 4 + 0] = v[0];
        scratch[w * 4 + 1] = v[1];
        scratch[w * 4 + 2] = v[2];
        scratch[w * 4 + 3] = v[3];
    }
    __syncthreads();
    if (tid < 32) {
        float x = scratch[tid];  // entry = warp (tid>>2), value (tid&3)
#pragma unroll
        for (int o = 16; o >= 4; o >>= 1) x += __shfl_xor_sync(FULLMASK, x, o);
        if (tid < 4) scratch[tid] = x;
    }
    __syncthreads();
    v[0] = scratch[0]; v[1] = scratch[1]; v[2] = scratch[2]; v[3] = scratch[3];
    __syncthreads();  // protect scratch for next call
}

// Reduce 8 independent values across a 256-thread block. scratch >= 64 floats.
// One call replaces two blockReduceSum4 calls (halves barrier traffic).
static __device__ __forceinline__ void blockReduceSum8(float* v, float* scratch, int tid) {
#pragma unroll
    for (int i = 0; i < 8; i++) {
#pragma unroll
        for (int o = 16; o; o >>= 1) v[i] += __shfl_xor_sync(FULLMASK, v[i], o);
    }
    if ((tid & 31) == 0) {
        int w = tid >> 5;
#pragma unroll
        for (int i = 0; i < 8; i++) scratch[w * 8 + i] = v[i];
    }
    __syncthreads();
    if (tid < 32) {
        float x = scratch[tid] + scratch[tid + 32];   // fold warps w and w+4
#pragma unroll
        for (int o = 16; o >= 8; o >>= 1) x += __shfl_xor_sync(FULLMASK, x, o);
        if (tid < 8) scratch[tid] = x;                // value i at scratch[i]
    }
    __syncthreads();
#pragma unroll
    for (int i = 0; i < 8; i++) v[i] = scratch[i];
    __syncthreads();  // protect scratch for next call
}

// ---------------------------------------------------------------------------
// Kernel 1: feature extraction. One block per row b. 256 threads = 8 warps.
// Stages the full 8x1000 tile in smem -> single pass over posteriors.
// ---------------------------------------------------------------------------
__global__ __launch_bounds__(256) void feat_kernel(
    const float* __restrict__ post, float* __restrict__ feats, int B)
{
    __shared__ float p_s[8000];
    __shared__ float mean_s[1000];
    __shared__ float lm_s[1000];
    __shared__ float maxs_s[8];
    __shared__ float red_s[32];
    __shared__ float s_mn;

    int b = blockIdx.x;
    int tid = threadIdx.x;

    // Load 8x1000 tile (32 KB) coalesced as float4.
    {
        const float4* src = (const float4*)(post + (size_t)b * 8000);
        float4* dst = (float4*)p_s;
        for (int i = tid; i < 2000; i += 256) dst[i] = src[i];
    }
    __syncthreads();

    // Stage A: per-class mean over experts, log(mean), per-class variance
    // (ddof=1), plus row-level accumulators.
    float ment = 0.f, vsum = 0.f, mn2 = 0.f;
    for (int c = tid; c < 1000; c += 256) {
        float pv[8];
        float s = 0.f;
#pragma unroll
        for (int e = 0; e < 8; e++) { pv[e] = p_s[e * 1000 + c]; s += pv[e]; }
        float m = s * 0.125f;
        float d2 = 0.f;
#pragma unroll
        for (int e = 0; e < 8; e++) { float d = pv[e] - m; d2 += d * d; }
        vsum += d2 * (1.f / 7.f);
        float lm = __logf(m + EPSF);
        mean_s[c] = m;
        lm_s[c] = lm;
        ment -= m * lm;
        mn2 += m * m;
    }
    {
        float v[4] = {ment, vsum, mn2, 0.f};
        blockReduceSum4(v, red_s, tid);
        if (tid == 0) {
            s_mn = fmaxf(sqrtf(v[2]), EPSF);
            size_t base = (size_t)b * 59;
            feats[base + 56] = clipf(v[0]);                   // mean_ent
            feats[base + 57] = clipf(v[1] * (1.f / 1000.f));  // mean_class_var
        }
    }
    __syncthreads();

    // Stage B: one warp per expert.
    int wid = tid >> 5, lane = tid & 31;
    {
        int e = wid;
        float ent = 0.f, kl = 0.f, dot = 0.f, pn2 = 0.f;
        float tk[5] = {-1e30f, -1e30f, -1e30f, -1e30f, -1e30f};
        for (int c = lane; c < 1000; c += 32) {
            float v = p_s[e * 1000 + c];
            float lv = __logf(v + EPSF);
            ent -= v * lv;
            kl += v * (lv - lm_s[c]);
            dot += v * mean_s[c];
            pn2 += v * v;
            float x = v;  // sorted-insert into local top-5
#pragma unroll
            for (int i = 0; i < 5; i++) {
                if (x > tk[i]) { float t = tk[i]; tk[i] = x; x = t; }
            }
        }
#pragma unroll
        for (int o = 16; o; o >>= 1) {
            ent += __shfl_xor_sync(FULLMASK, ent, o);
            kl  += __shfl_xor_sync(FULLMASK, kl, o);
            dot += __shfl_xor_sync(FULLMASK, dot, o);
            pn2 += __shfl_xor_sync(FULLMASK, pn2, o);
        }
        // Merge top-5 across warp: pop warp max 5 times.
        float res[5];
#pragma unroll
        for (int i = 0; i < 5; i++) {
            float h = tk[0];
            float mx = h;
#pragma unroll
            for (int o = 16; o; o >>= 1) mx = fmaxf(mx, __shfl_xor_sync(FULLMASK, mx, o));
            res[i] = mx;
            unsigned msk = __ballot_sync(FULLMASK, h == mx);
            int leader = __ffs(msk) - 1;
            if (lane == leader) {
                tk[0] = tk[1]; tk[1] = tk[2]; tk[2] = tk[3]; tk[3] = tk[4]; tk[4] = -1e30f;
            }
        }
        if (lane == 0) {
            float mass = res[0] + res[1] + res[2] + res[3] + res[4];
            float pn = fmaxf(sqrtf(pn2), EPSF);
            float cosv = dot / (pn * s_mn);
            size_t base = (size_t)b * 59;
            feats[base + 0  + e] = clipf(ent);
            feats[base + 8  + e] = clipf(mass);
            feats[base + 16 + e] = clipf(1.0f - mass);
            feats[base + 24 + e] = clipf(res[0]);
            feats[base + 32 + e] = clipf(res[0] - res[1]);
            feats[base + 40 + e] = clipf(cosv);
            feats[base + 48 + e] = clipf(kl);
            maxs_s[e] = res[0];
        }
    }
    __syncthreads();
    if (tid == 0) {
        float s = 0.f;
#pragma unroll
        for (int e = 0; e < 8; e++) s += maxs_s[e];
        float mu = s * 0.125f, d2 = 0.f;
#pragma unroll
        for (int e = 0; e < 8; e++) { float d = maxs_s[e] - mu; d2 += d * d; }
        feats[(size_t)b * 59 + 58] = clipf(sqrtf(d2 * (1.f / 7.f)));
    }
}

// ---------------------------------------------------------------------------
// Kernel 2: fused 3-layer MLP (+2 LN, relu, softmax). Persistent blocks,
// all weights resident in dynamic smem. 4 rows per pass so each weight LDS
// feeds 4 FMAs; activations read as float4 broadcasts (conflict-free).
// ---------------------------------------------------------------------------
#define MLP_SMEM_FLOATS 53224

__global__ __launch_bounds__(256, 1) void mlp_kernel(
    const float* __restrict__ feats,
    const float* __restrict__ W1, const float* __restrict__ b1,
    const float* __restrict__ g1, const float* __restrict__ be1,
    const float* __restrict__ W2, const float* __restrict__ b2,
    const float* __restrict__ g2, const float* __restrict__ be2,
    const float* __restrict__ W3, const float* __restrict__ b3,
    float* __restrict__ wout, float* __restrict__ lout, int B)
{
    extern __shared__ float sm[];
    float* sW1  = sm;             // 60*256 = 15360 (row 59 zero-padded)
    float* sW2  = sW1 + 15360;    // 256*128 = 32768
    float* sW3  = sW2 + 32768;    // 128*8   = 1024
    float* sb1  = sW3 + 1024;     // 256
    float* sg1  = sb1 + 256;
    float* sbe1 = sg1 + 256;
    float* sb2  = sbe1 + 256;     // 128
    float* sg2  = sb2 + 128;
    float* sbe2 = sg2 + 128;
    float* sb3  = sbe2 + 128;     // 8
    float* fs   = sb3 + 8;        // 4 * 64 (padded feat rows)
    float* h1s  = fs + 256;       // 4 * 256
    float* h2p  = h1s + 1024;     // 4 * 256 (split-k partials)
    float* h2s  = h2p + 1024;     // 4 * 128
    float* lgs  = h2s + 512;      // 4 * 8
    float* red  = lgs + 32;       // 64

    int tid = threadIdx.x;

    for (int i = tid; i < 15104; i += 256) sW1[i] = W1[i];
    sW1[15104 + tid] = 0.f;  // pad row k=59
    for (int i = tid; i < 32768; i += 256) sW2[i] = W2[i];
    for (int i = tid; i < 1024; i += 256) sW3[i] = W3[i];
    sb1[tid] = b1[tid]; sg1[tid] = g1[tid]; sbe1[tid] = be1[tid];
    if (tid < 128) { sb2[tid] = b2[tid]; sg2[tid] = g2[tid]; sbe2[tid] = be2[tid]; }
    if (tid < 8) sb3[tid] = b3[tid];
    if ((tid & 63) >= 59) fs[tid] = 0.f;  // pads for all 4 feat rows
    __syncthreads();

    int ngroups = (B + 3) >> 2;
    for (int g = blockIdx.x; g < ngroups; g += gridDim.x) {
        int r0 = g * 4;
        // load 4 feature rows (59 each) into padded smem rows of 64
        if (tid < 236) {
            int r = tid / 59, c = tid - r * 59;
            int ri = r0 + r;
            fs[r * 64 + c] = (ri < B) ? feats[(size_t)ri * 59 + c] : 0.f;
        }
        __syncthreads();

        // ---- layer 1: output col = tid, 4 rows at once ----
        float a[4];
#pragma unroll
        for (int r = 0; r < 4; r++) a[r] = sb1[tid];
#pragma unroll
        for (int k = 0; k < 60; k += 4) {
            float4 f[4];
#pragma unroll
            for (int r = 0; r < 4; r++) f[r] = *(const float4*)(fs + r * 64 + k);
            float w;
            w = sW1[(k + 0) * 256 + tid];
#pragma unroll
            for (int r = 0; r < 4; r++) a[r] += f[r].x * w;
            w = sW1[(k + 1) * 256 + tid];
#pragma unroll
            for (int r = 0; r < 4; r++) a[r] += f[r].y * w;
            w = sW1[(k + 2) * 256 + tid];
#pragma unroll
            for (int r = 0; r < 4; r++) a[r] += f[r].z * w;
            w = sW1[(k + 3) * 256 + tid];
#pragma unroll
            for (int r = 0; r < 4; r++) a[r] += f[r].w * w;
        }
        {
            float v[8] = {a[0], a[0] * a[0], a[1], a[1] * a[1],
                          a[2], a[2] * a[2], a[3], a[3] * a[3]};
            blockReduceSum8(v, red, tid);
            const float inv = 1.f / 256.f;
#pragma unroll
            for (int r = 0; r < 4; r++) {
                float mu = v[2 * r] * inv;
                float var = fmaf(-mu, mu, v[2 * r + 1] * inv);
                float n = fmaxf((a[r] - mu) * rsqrtf(var + LN_EPSF) * sg1[tid] + sbe1[tid], 0.f);
                h1s[r * 256 + tid] = n;
            }
        }
        __syncthreads();

        // ---- layer 2: split-k (2 halves of 128), col = tid & 127 ----
        int col = tid & 127, kb = (tid >> 7) << 7;
        float c4[4] = {0.f, 0.f, 0.f, 0.f};
#pragma unroll 8
        for (int k = 0; k < 128; k += 4) {
            float4 h[4];
#pragma unroll
            for (int r = 0; r < 4; r++) h[r] = *(const float4*)(h1s + r * 256 + kb + k);
            float w;
            w = sW2[(kb + k + 0) * 128 + col];
#pragma unroll
            for (int r = 0; r < 4; r++) c4[r] += h[r].x * w;
            w = sW2[(kb + k + 1) * 128 + col];
#pragma unroll
            for (int r = 0; r < 4; r++) c4[r] += h[r].y * w;
            w = sW2[(kb + k + 2) * 128 + col];
#pragma unroll
            for (int r = 0; r < 4; r++) c4[r] += h[r].z * w;
            w = sW2[(kb + k + 3) * 128 + col];
#pragma unroll
            for (int r = 0; r < 4; r++) c4[r] += h[r].w * w;
        }
#pragma unroll
        for (int r = 0; r < 4; r++) h2p[r * 256 + tid] = c4[r];
        __syncthreads();
        float z[4] = {0.f, 0.f, 0.f, 0.f};
        if (tid < 128) {
#pragma unroll
            for (int r = 0; r < 4; r++)
                z[r] = h2p[r * 256 + tid] + h2p[r * 256 + 128 + tid] + sb2[tid];
        }
        {
            float u[8] = {z[0], z[0] * z[0], z[1], z[1] * z[1],
                          z[2], z[2] * z[2], z[3], z[3] * z[3]};
            blockReduceSum8(u, red, tid);  // threads >=128 contribute 0
            const float inv = 1.f / 128.f;
            if (tid < 128) {
#pragma unroll
                for (int r = 0; r < 4; r++) {
                    float mu = u[2 * r] * inv;
                    float var = fmaf(-mu, mu, u[2 * r + 1] * inv);
                    float m = fmaxf((z[r] - mu) * rsqrtf(var + LN_EPSF) * sg2[tid] + sbe2[tid], 0.f);
                    h2s[r * 128 + tid] = m;
                }
            }
        }
        __syncthreads();

        // ---- layer 3: warp w -> output col w (all 4 rows) ----
        int wid = tid >> 5, lane = tid & 31;
        float s4[4] = {0.f, 0.f, 0.f, 0.f};
#pragma unroll
        for (int kk = 0; kk < 128; kk += 32) {
            int k = kk + lane;
            float w3 = sW3[k * 8 + wid];
#pragma unroll
            for (int r = 0; r < 4; r++) s4[r] += h2s[r * 128 + k] * w3;
        }
#pragma unroll
        for (int o = 16; o; o >>= 1) {
#pragma unroll
            for (int r = 0; r < 4; r++) s4[r] += __shfl_xor_sync(FULLMASK, s4[r], o);
        }
        if (lane == 0) {
#pragma unroll
            for (int r = 0; r < 4; r++) {
                float l = s4[r] + sb3[wid];
                lgs[r * 8 + wid] = l;
                int ri = r0 + r;
                if (ri < B) lout[(size_t)ri * 8 + wid] = l;
            }
        }
        __syncthreads();

        // ---- softmax over 8 logits: threads 0..31, row = tid>>3 ----
        if (tid < 32) {
            int r = tid >> 3, cc = tid & 7;
            const float* L = lgs + r * 8;
            float mx = L[0];
#pragma unroll
            for (int i = 1; i < 8; i++) mx = fmaxf(mx, L[i]);
            float ssum = 0.f;
#pragma unroll
            for (int i = 0; i < 8; i++) ssum += __expf(L[i] - mx);
            float wv = __expf(L[cc] - mx) / ssum;
            int ri = r0 + r;
            if (ri < B) wout[(size_t)ri * 8 + cc] = wv;
        }
        __syncthreads();
    }
}

// ---------------------------------------------------------------------------
extern "C" void kernel_launch(void* const* d_in, const int* in_sizes, int n_in,
                              void* d_out, int out_size)
{
    const float* post = (const float*)d_in[0];
    const float* W1   = (const float*)d_in[1];
    const float* b1   = (const float*)d_in[2];
    const float* g1   = (const float*)d_in[3];
    const float* be1  = (const float*)d_in[4];
    const float* W2   = (const float*)d_in[5];
    const float* b2   = (const float*)d_in[6];
    const float* g2   = (const float*)d_in[7];
    const float* be2  = (const float*)d_in[8];
    const float* W3   = (const float*)d_in[9];
    const float* b3   = (const float*)d_in[10];

    int B = in_sizes[0] / 8000;  // E=8, C=1000

    float* out  = (float*)d_out;
    float* wout = out;                      // weights: B*8
    float* lout = out + (size_t)B * 8;      // logits:  B*8
    float* fout = out + (size_t)B * 16;     // feats:   B*59

    feat_kernel<<<B, 256>>>(post, fout, B);

    // Unconditional (no static guards — harness determinism rule).
    cudaFuncSetAttribute(mlp_kernel, cudaFuncAttributeMaxDynamicSharedMemorySize,
                         MLP_SMEM_FLOATS * sizeof(float));
    mlp_kernel<<<148, 256, MLP_SMEM_FLOATS * sizeof(float)>>>(
        fout, W1, b1, g1, be1, W2, b2, g2, be2, W3, b3, wout, lout, B);
}

// round 12
// speedup vs baseline: 1.1077x; 1.1077x over previous
#include <cuda_runtime.h>

#define FULLMASK 0xffffffffu
#define EPSF 1e-8f
#define LN_EPSF 1e-5f

static __device__ __forceinline__ float clipf(float x) {
    return fminf(fmaxf(x, -100.0f), 100.0f);
}

// Reduce 4 values across a 256-thread block. scratch >= 32 floats.
static __device__ __forceinline__ void blockReduceSum4(float* v, float* scratch, int tid) {
#pragma unroll
    for (int i = 0; i < 4; i++) {
#pragma unroll
        for (int o = 16; o; o >>= 1) v[i] += __shfl_xor_sync(FULLMASK, v[i], o);
    }
    if ((tid & 31) == 0) {
        int w = tid >> 5;
#pragma unroll
        for (int i = 0; i < 4; i++) scratch[w * 4 + i] = v[i];
    }
    __syncthreads();
    if (tid < 32) {
        float x = scratch[tid];
#pragma unroll
        for (int o = 16; o >= 4; o >>= 1) x += __shfl_xor_sync(FULLMASK, x, o);
        if (tid < 4) scratch[tid] = x;
    }
    __syncthreads();
    v[0] = scratch[0]; v[1] = scratch[1]; v[2] = scratch[2]; v[3] = scratch[3];
    __syncthreads();
}

// Reduce 8 values across a 256-thread TEAM (both teams call in lockstep;
// __syncthreads is block-wide and both teams execute identical sequences).
static __device__ __forceinline__ void teamReduceSum8(float* v, float* scratch, int ttid) {
#pragma unroll
    for (int i = 0; i < 8; i++) {
#pragma unroll
        for (int o = 16; o; o >>= 1) v[i] += __shfl_xor_sync(FULLMASK, v[i], o);
    }
    if ((ttid & 31) == 0) {
        int w = ttid >> 5;
#pragma unroll
        for (int i = 0; i < 8; i++) scratch[w * 8 + i] = v[i];
    }
    __syncthreads();
    if (ttid < 32) {
        float x = scratch[ttid] + scratch[ttid + 32];   // fold warps w and w+4
#pragma unroll
        for (int o = 16; o >= 8; o >>= 1) x += __shfl_xor_sync(FULLMASK, x, o);
        if (ttid < 8) scratch[ttid] = x;
    }
    __syncthreads();
#pragma unroll
    for (int i = 0; i < 8; i++) v[i] = scratch[i];
    __syncthreads();
}

// ---------------------------------------------------------------------------
// Kernel 1: feature extraction. One block per row. 256 threads.
// No smem staging: stage A streams global (DRAM), stage B re-reads from L2.
// float4 granularity everywhere; guarded top-5 insertion.
// ---------------------------------------------------------------------------
__global__ __launch_bounds__(256) void feat_kernel(
    const float* __restrict__ post, float* __restrict__ feats, int B)
{
    __shared__ float4 mean4_s[250];
    __shared__ float4 lm4_s[250];
    __shared__ float maxs_s[8];
    __shared__ float red_s[32];
    __shared__ float s_mn;

    int b = blockIdx.x;
    int tid = threadIdx.x;
    const float4* row4 = (const float4*)(post + (size_t)b * 8000);  // 2000 float4s

    // ---- Stage A: per-class mean/var over experts; threads 0..249, 4 classes each.
    float ment = 0.f, vsum = 0.f, mn2 = 0.f;
    if (tid < 250) {
        float p[8][4];
#pragma unroll
        for (int e = 0; e < 8; e++) {
            float4 t = row4[e * 250 + tid];
            p[e][0] = t.x; p[e][1] = t.y; p[e][2] = t.z; p[e][3] = t.w;
        }
        float m[4], lm[4];
#pragma unroll
        for (int j = 0; j < 4; j++) {
            float s = 0.f;
#pragma unroll
            for (int e = 0; e < 8; e++) s += p[e][j];
            m[j] = s * 0.125f;
            float d2 = 0.f;
#pragma unroll
            for (int e = 0; e < 8; e++) { float d = p[e][j] - m[j]; d2 += d * d; }
            vsum += d2 * (1.f / 7.f);
            lm[j] = __logf(m[j] + EPSF);
            ment -= m[j] * lm[j];
            mn2 = fmaf(m[j], m[j], mn2);
        }
        mean4_s[tid] = make_float4(m[0], m[1], m[2], m[3]);
        lm4_s[tid]   = make_float4(lm[0], lm[1], lm[2], lm[3]);
    }
    {
        float v[4] = {ment, vsum, mn2, 0.f};
        blockReduceSum4(v, red_s, tid);
        if (tid == 0) {
            s_mn = fmaxf(sqrtf(v[2]), EPSF);
            size_t base = (size_t)b * 59;
            feats[base + 56] = clipf(v[0]);                   // mean_ent
            feats[base + 57] = clipf(v[1] * (1.f / 1000.f));  // mean_class_var
        }
    }
    __syncthreads();  // s_mn + mean/lm tables visible

    // ---- Stage B: one warp per expert; float4 reads from L2-hot global.
    int wid = tid >> 5, lane = tid & 31;
    {
        int e = wid;
        float ent = 0.f, kl = 0.f, dot = 0.f, pn2 = 0.f;
        float tk[5] = {-1e30f, -1e30f, -1e30f, -1e30f, -1e30f};
        for (int c4 = lane; c4 < 250; c4 += 32) {
            float4 v4 = row4[e * 250 + c4];   // L2 hit (just read in stage A)
            float4 lm4 = lm4_s[c4];
            float4 m4 = mean4_s[c4];
            float vv[4] = {v4.x, v4.y, v4.z, v4.w};
            float ll[4] = {lm4.x, lm4.y, lm4.z, lm4.w};
            float mm[4] = {m4.x, m4.y, m4.z, m4.w};
#pragma unroll
            for (int j = 0; j < 4; j++) {
                float v = vv[j];
                float lv = __logf(v + EPSF);
                ent -= v * lv;
                kl  = fmaf(v, lv - ll[j], kl);
                dot = fmaf(v, mm[j], dot);
                pn2 = fmaf(v, v, pn2);
                if (v > tk[4]) {                     // rare: full insert
                    float x = v;
#pragma unroll
                    for (int i = 0; i < 5; i++) {
                        if (x > tk[i]) { float t = tk[i]; tk[i] = x; x = t; }
                    }
                }
            }
        }
#pragma unroll
        for (int o = 16; o; o >>= 1) {
            ent += __shfl_xor_sync(FULLMASK, ent, o);
            kl  += __shfl_xor_sync(FULLMASK, kl, o);
            dot += __shfl_xor_sync(FULLMASK, dot, o);
            pn2 += __shfl_xor_sync(FULLMASK, pn2, o);
        }
        // Merge top-5 across warp: pop warp max 5 times (duplicate-safe).
        float res[5];
#pragma unroll
        for (int i = 0; i < 5; i++) {
            float h = tk[0];
            float mx = h;
#pragma unroll
            for (int o = 16; o; o >>= 1) mx = fmaxf(mx, __shfl_xor_sync(FULLMASK, mx, o));
            res[i] = mx;
            unsigned msk = __ballot_sync(FULLMASK, h == mx);
            int leader = __ffs(msk) - 1;
            if (lane == leader) {
                tk[0] = tk[1]; tk[1] = tk[2]; tk[2] = tk[3]; tk[3] = tk[4]; tk[4] = -1e30f;
            }
        }
        if (lane == 0) {
            float mass = res[0] + res[1] + res[2] + res[3] + res[4];
            float pn = fmaxf(sqrtf(pn2), EPSF);
            float cosv = dot / (pn * s_mn);
            size_t base = (size_t)b * 59;
            feats[base + 0  + e] = clipf(ent);
            feats[base + 8  + e] = clipf(mass);
            feats[base + 16 + e] = clipf(1.0f - mass);
            feats[base + 24 + e] = clipf(res[0]);
            feats[base + 32 + e] = clipf(res[0] - res[1]);
            feats[base + 40 + e] = clipf(cosv);
            feats[base + 48 + e] = clipf(kl);
            maxs_s[e] = res[0];
        }
    }
    __syncthreads();
    if (tid == 0) {
        float s = 0.f;
#pragma unroll
        for (int e = 0; e < 8; e++) s += maxs_s[e];
        float mu = s * 0.125f, d2 = 0.f;
#pragma unroll
        for (int e = 0; e < 8; e++) { float d = maxs_s[e] - mu; d2 += d * d; }
        feats[(size_t)b * 59 + 58] = clipf(sqrtf(d2 * (1.f / 7.f)));
    }
}

// ---------------------------------------------------------------------------
// Kernel 2: fused MLP. 512 threads = two 256-thread teams sharing the
// smem-resident weights; each team does 4 rows per pass (8 rows/block/pass).
// Doubles warps/SM (occ 12.5% -> 25%) to cover LDS latency + barriers.
// ---------------------------------------------------------------------------
#define MLP_SMEM_FLOATS 56136

__global__ __launch_bounds__(512, 1) void mlp_kernel(
    const float* __restrict__ feats,
    const float* __restrict__ W1, const float* __restrict__ b1,
    const float* __restrict__ g1, const float* __restrict__ be1,
    const float* __restrict__ W2, const float* __restrict__ b2,
    const float* __restrict__ g2, const float* __restrict__ be2,
    const float* __restrict__ W3, const float* __restrict__ b3,
    float* __restrict__ wout, float* __restrict__ lout, int B)
{
    extern __shared__ float sm[];
    float* sW1  = sm;             // 60*256 (row 59 zero-padded)
    float* sW2  = sW1 + 15360;    // 256*128
    float* sW3  = sW2 + 32768;    // 128*8
    float* sb1  = sW3 + 1024;
    float* sg1  = sb1 + 256;
    float* sbe1 = sg1 + 256;
    float* sb2  = sbe1 + 256;
    float* sg2  = sb2 + 128;
    float* sbe2 = sg2 + 128;
    float* sb3  = sbe2 + 128;     // 8
    float* fs   = sb3 + 8;        // 8 * 64
    float* h1s  = fs + 512;       // 8 * 256
    float* h2p  = h1s + 2048;     // 8 * 256
    float* h2s  = h2p + 2048;     // 8 * 128
    float* lgs  = h2s + 1024;     // 8 * 8
    float* red  = lgs + 64;       // 2 * 64

    int tid  = threadIdx.x;
    int team = tid >> 8;          // 0 or 1
    int ttid = tid & 255;

    for (int i = tid; i < 15104; i += 512) sW1[i] = W1[i];
    if (tid < 256) sW1[15104 + tid] = 0.f;           // pad row k=59
    for (int i = tid; i < 32768; i += 512) sW2[i] = W2[i];
    for (int i = tid; i < 1024; i += 512) sW3[i] = W3[i];
    if (tid < 256) { sb1[tid] = b1[tid]; sg1[tid] = g1[tid]; sbe1[tid] = be1[tid]; }
    if (tid < 128) { sb2[tid] = b2[tid]; sg2[tid] = g2[tid]; sbe2[tid] = be2[tid]; }
    if (tid < 8) sb3[tid] = b3[tid];
    if ((tid & 63) >= 59) fs[tid] = 0.f;             // pads for all 8 feat rows
    __syncthreads();

    float* tfs  = fs  + team * 256;
    float* th1  = h1s + team * 1024;
    float* th2p = h2p + team * 1024;
    float* th2s = h2s + team * 512;
    float* tlg  = lgs + team * 32;
    float* tred = red + team * 64;

    int ngroups = (B + 7) >> 3;
    for (int g = blockIdx.x; g < ngroups; g += gridDim.x) {
        int r0 = g * 8 + team * 4;
        // load 8 feature rows (59 each) into padded smem rows of 64
        if (tid < 472) {
            int r = tid / 59, c = tid - r * 59;
            int ri = g * 8 + r;
            fs[r * 64 + c] = (ri < B) ? feats[(size_t)ri * 59 + c] : 0.f;
        }
        __syncthreads();

        // ---- layer 1: output col = ttid, 4 team rows at once ----
        float a[4];
#pragma unroll
        for (int r = 0; r < 4; r++) a[r] = sb1[ttid];
#pragma unroll
        for (int k = 0; k < 60; k += 4) {
            float4 f[4];
#pragma unroll
            for (int r = 0; r < 4; r++) f[r] = *(const float4*)(tfs + r * 64 + k);
            float w;
            w = sW1[(k + 0) * 256 + ttid];
#pragma unroll
            for (int r = 0; r < 4; r++) a[r] = fmaf(f[r].x, w, a[r]);
            w = sW1[(k + 1) * 256 + ttid];
#pragma unroll
            for (int r = 0; r < 4; r++) a[r] = fmaf(f[r].y, w, a[r]);
            w = sW1[(k + 2) * 256 + ttid];
#pragma unroll
            for (int r = 0; r < 4; r++) a[r] = fmaf(f[r].z, w, a[r]);
            w = sW1[(k + 3) * 256 + ttid];
#pragma unroll
            for (int r = 0; r < 4; r++) a[r] = fmaf(f[r].w, w, a[r]);
        }
        {
            float v[8] = {a[0], a[0] * a[0], a[1], a[1] * a[1],
                          a[2], a[2] * a[2], a[3], a[3] * a[3]};
            teamReduceSum8(v, tred, ttid);
            const float inv = 1.f / 256.f;
#pragma unroll
            for (int r = 0; r < 4; r++) {
                float mu = v[2 * r] * inv;
                float var = fmaf(-mu, mu, v[2 * r + 1] * inv);
                float n = fmaxf((a[r] - mu) * rsqrtf(var + LN_EPSF) * sg1[ttid] + sbe1[ttid], 0.f);
                th1[r * 256 + ttid] = n;
            }
        }
        __syncthreads();

        // ---- layer 2: split-k (2 halves of 128) within team ----
        int col = ttid & 127, kb = (ttid >> 7) << 7;
        float c4[4] = {0.f, 0.f, 0.f, 0.f};
#pragma unroll 8
        for (int k = 0; k < 128; k += 4) {
            float4 h[4];
#pragma unroll
            for (int r = 0; r < 4; r++) h[r] = *(const float4*)(th1 + r * 256 + kb + k);
            float w;
            w = sW2[(kb + k + 0) * 128 + col];
#pragma unroll
            for (int r = 0; r < 4; r++) c4[r] = fmaf(h[r].x, w, c4[r]);
            w = sW2[(kb + k + 1) * 128 + col];
#pragma unroll
            for (int r = 0; r < 4; r++) c4[r] = fmaf(h[r].y, w, c4[r]);
            w = sW2[(kb + k + 2) * 128 + col];
#pragma unroll
            for (int r = 0; r < 4; r++) c4[r] = fmaf(h[r].z, w, c4[r]);
            w = sW2[(kb + k + 3) * 128 + col];
#pragma unroll
            for (int r = 0; r < 4; r++) c4[r] = fmaf(h[r].w, w, c4[r]);
        }
#pragma unroll
        for (int r = 0; r < 4; r++) th2p[r * 256 + ttid] = c4[r];
        __syncthreads();
        float z[4] = {0.f, 0.f, 0.f, 0.f};
        if (ttid < 128) {
#pragma unroll
            for (int r = 0; r < 4; r++)
                z[r] = th2p[r * 256 + ttid] + th2p[r * 256 + 128 + ttid] + sb2[ttid];
        }
        {
            float u[8] = {z[0], z[0] * z[0], z[1], z[1] * z[1],
                          z[2], z[2] * z[2], z[3], z[3] * z[3]};
            teamReduceSum8(u, tred, ttid);  // ttid >=128 contribute 0
            const float inv = 1.f / 128.f;
            if (ttid < 128) {
#pragma unroll
                for (int r = 0; r < 4; r++) {
                    float mu = u[2 * r] * inv;
                    float var = fmaf(-mu, mu, u[2 * r + 1] * inv);
                    float m = fmaxf((z[r] - mu) * rsqrtf(var + LN_EPSF) * sg2[ttid] + sbe2[ttid], 0.f);
                    th2s[r * 128 + ttid] = m;
                }
            }
        }
        __syncthreads();

        // ---- layer 3: team warp wt -> output col wt (4 team rows) ----
        int wt = ttid >> 5, lane = ttid & 31;
        float s4[4] = {0.f, 0.f, 0.f, 0.f};
#pragma unroll
        for (int kk = 0; kk < 128; kk += 32) {
            int k = kk + lane;
            float w3 = sW3[k * 8 + wt];
#pragma unroll
            for (int r = 0; r < 4; r++) s4[r] = fmaf(th2s[r * 128 + k], w3, s4[r]);
        }
#pragma unroll
        for (int o = 16; o; o >>= 1) {
#pragma unroll
            for (int r = 0; r < 4; r++) s4[r] += __shfl_xor_sync(FULLMASK, s4[r], o);
        }
        if (lane == 0) {
#pragma unroll
            for (int r = 0; r < 4; r++) {
                float l = s4[r] + sb3[wt];
                tlg[r * 8 + wt] = l;
                int ri = r0 + r;
                if (ri < B) lout[(size_t)ri * 8 + wt] = l;
            }
        }
        __syncthreads();

        // ---- softmax over 8 logits: per team, threads 0..31 ----
        if (ttid < 32) {
            int r = ttid >> 3, cc = ttid & 7;
            const float* L = tlg + r * 8;
            float mx = L[0];
#pragma unroll
            for (int i = 1; i < 8; i++) mx = fmaxf(mx, L[i]);
            float ssum = 0.f;
#pragma unroll
            for (int i = 0; i < 8; i++) ssum += __expf(L[i] - mx);
            float wv = __expf(L[cc] - mx) / ssum;
            int ri = r0 + r;
            if (ri < B) wout[(size_t)ri * 8 + cc] = wv;
        }
        __syncthreads();
    }
}

// ---------------------------------------------------------------------------
extern "C" void kernel_launch(void* const* d_in, const int* in_sizes, int n_in,
                              void* d_out, int out_size)
{
    const float* post = (const float*)d_in[0];
    const float* W1   = (const float*)d_in[1];
    const float* b1   = (const float*)d_in[2];
    const float* g1   = (const float*)d_in[3];
    const float* be1  = (const float*)d_in[4];
    const float* W2   = (const float*)d_in[5];
    const float* b2   = (const float*)d_in[6];
    const float* g2   = (const float*)d_in[7];
    const float* be2  = (const float*)d_in[8];
    const float* W3   = (const float*)d_in[9];
    const float* b3   = (const float*)d_in[10];

    int B = in_sizes[0] / 8000;  // E=8, C=1000

    float* out  = (float*)d_out;
    float* wout = out;                      // weights: B*8
    float* lout = out + (size_t)B * 8;      // logits:  B*8
    float* fout = out + (size_t)B * 16;     // feats:   B*59

    feat_kernel<<<B, 256>>>(post, fout, B);

    cudaFuncSetAttribute(mlp_kernel, cudaFuncAttributeMaxDynamicSharedMemorySize,
                         MLP_SMEM_FLOATS * sizeof(float));
    mlp_kernel<<<148, 512, MLP_SMEM_FLOATS * sizeof(float)>>>(
        fout, W1, b1, g1, be1, W2, b2, g2, be2, W3, b3, wout, lout, B);
}